// round 1
// baseline (speedup 1.0000x reference)
#include <cuda_runtime.h>

// Problem constants
#define B_    2
#define NSEQ  2048
#define DIM_  1024
#define H_    16
#define HD_   64
#define SCALE_F 0.125f   // HD^-0.5

// Scratch (device globals: allocation-free contract)
__device__ float g_Q [B_*H_*NSEQ*HD_];   // [bh][n][d], pre-scaled by SCALE
__device__ float g_Kt[B_*H_*HD_*NSEQ];   // [bh][d][n]  (transposed for coalesced score loads)
__device__ float g_V [B_*H_*NSEQ*HD_];   // [bh][n][d]
__device__ float g_AO[B_*NSEQ*DIM_];     // attention output [b*n][dim]

// ---------------------------------------------------------------------------
// Tiled SGEMM: C[M,N] = A[M,K] @ W[N,K]^T + bias[N]
// MODE 0: QKV scatter epilogue -> g_Q/g_Kt/g_V.  MODE 1: plain write to C.
// BM=BN=128, BK=16, 256 threads, 8x8 per-thread tile.
// ---------------------------------------------------------------------------
template<int MODE>
__global__ __launch_bounds__(256)
void gemm_kernel(const float* __restrict__ A, const float* __restrict__ W,
                 const float* __restrict__ bias, float* __restrict__ C,
                 int M, int N, int K)
{
    __shared__ float As[16][128];
    __shared__ float Bs[16][128];

    const int tid  = threadIdx.x;
    const int tx   = tid & 15;
    const int ty   = tid >> 4;
    const int row0 = blockIdx.y * 128;
    const int col0 = blockIdx.x * 128;

    const float* Ap = (MODE == 1) ? (const float*)g_AO : A;

    float acc[8][8];
#pragma unroll
    for (int i = 0; i < 8; i++)
#pragma unroll
        for (int j = 0; j < 8; j++) acc[i][j] = 0.0f;

    for (int k0 = 0; k0 < K; k0 += 16) {
        // Stage A tile: 128 rows x 16 k  (512 float4, 2 per thread)
#pragma unroll
        for (int i = 0; i < 2; i++) {
            int f  = tid + i * 256;
            int r  = f >> 2;
            int kp = (f & 3) * 4;
            float4 v = *(const float4*)&Ap[(row0 + r) * K + k0 + kp];
            As[kp + 0][r] = v.x; As[kp + 1][r] = v.y;
            As[kp + 2][r] = v.z; As[kp + 3][r] = v.w;
        }
        // Stage W tile: 128 cols x 16 k
#pragma unroll
        for (int i = 0; i < 2; i++) {
            int f  = tid + i * 256;
            int c  = f >> 2;
            int kp = (f & 3) * 4;
            float4 v = *(const float4*)&W[(col0 + c) * K + k0 + kp];
            Bs[kp + 0][c] = v.x; Bs[kp + 1][c] = v.y;
            Bs[kp + 2][c] = v.z; Bs[kp + 3][c] = v.w;
        }
        __syncthreads();

#pragma unroll
        for (int kk = 0; kk < 16; kk++) {
            float a[8], b[8];
            *(float4*)&a[0] = *(const float4*)&As[kk][ty * 8];
            *(float4*)&a[4] = *(const float4*)&As[kk][ty * 8 + 4];
            *(float4*)&b[0] = *(const float4*)&Bs[kk][tx * 8];
            *(float4*)&b[4] = *(const float4*)&Bs[kk][tx * 8 + 4];
#pragma unroll
            for (int i = 0; i < 8; i++)
#pragma unroll
                for (int j = 0; j < 8; j++)
                    acc[i][j] += a[i] * b[j];
        }
        __syncthreads();
    }

    if (MODE == 0) {
        // Scatter QKV: column c = which*1024 + h*64 + d
#pragma unroll
        for (int i = 0; i < 8; i++) {
            int r = row0 + ty * 8 + i;
            int b = r >> 11;           // / NSEQ
            int n = r & (NSEQ - 1);
#pragma unroll
            for (int j = 0; j < 8; j++) {
                int c   = col0 + tx * 8 + j;
                float v = acc[i][j] + bias[c];
                int which = c >> 10;
                int rem   = c & 1023;
                int h     = rem >> 6;
                int d     = rem & 63;
                int bh    = b * H_ + h;
                if (which == 0)      g_Q [(bh * NSEQ + n) * HD_ + d] = v * SCALE_F;
                else if (which == 1) g_Kt[(bh * HD_ + d) * NSEQ + n] = v;
                else                 g_V [(bh * NSEQ + n) * HD_ + d] = v;
            }
        }
    } else {
#pragma unroll
        for (int i = 0; i < 8; i++) {
            int r = row0 + ty * 8 + i;
#pragma unroll
            for (int j = 0; j < 8; j++) {
                int c = col0 + tx * 8 + j;
                C[r * N + c] = acc[i][j] + bias[c];
            }
        }
    }
}

// ---------------------------------------------------------------------------
// Flash-style focal attention.
// Block: 64 q-rows of one (b,h); 256 threads as 16(ty: q-groups) x 16(tx).
// Key chunks of 64. Per-thread 4x4 micro-tiles for both S=QK^T and O=P V.
// Online stats per q row: m (max), Z = sum exp(s-m), S2 = sum exp(g*(s-m)),
// A = sum exp(g*(s-m)) * v.  out = alpha*A / (alpha*S2 + 1e-6 * Z^g).
// ---------------------------------------------------------------------------
__global__ __launch_bounds__(256)
void flash_kernel(const float* __restrict__ falpha, const float* __restrict__ fgamma)
{
    __shared__ float Qs[64][64];   // [d][q]
    __shared__ float KP[64][64];   // K as [d][k]; reused as P [k][q-swizzled]
    __shared__ float Vs[64][64];   // [k][d]

    const int tid = threadIdx.x;
    const int tx  = tid & 15;
    const int ty  = tid >> 4;
    const int bh  = blockIdx.y;
    const int q0  = blockIdx.x * 64;

    const float gam   = fgamma[0];
    const float alpha = falpha[0];
    const bool  g2    = (gam == 2.0f);

    // Load Q tile (already scaled), transpose to [d][q]
    const float* Qg = g_Q + (bh * NSEQ + q0) * HD_;
#pragma unroll
    for (int i = 0; i < 16; i++) {
        int idx = tid + i * 256;
        Qs[idx & 63][idx >> 6] = Qg[idx];
    }

    float m[4], Z[4], S2[4], O[4][4];
#pragma unroll
    for (int i = 0; i < 4; i++) {
        m[i] = -1e30f; Z[i] = 0.0f; S2[i] = 0.0f;
#pragma unroll
        for (int j = 0; j < 4; j++) O[i][j] = 0.0f;
    }

    const float* Ktg = g_Kt + bh * HD_ * NSEQ;
    const float* Vg  = g_V  + bh * NSEQ * HD_;

    for (int k0 = 0; k0 < NSEQ; k0 += 64) {
        // Stage K [d][k] and V [k][d]
#pragma unroll
        for (int i = 0; i < 16; i++) {
            int idx = tid + i * 256;
            int r = idx >> 6, c = idx & 63;
            KP[r][c] = Ktg[r * NSEQ + k0 + c];
            Vs[r][c] = Vg[(k0 + r) * HD_ + c];
        }
        __syncthreads();

        // S = Q K^T (scale folded into Q)
        float s[4][4];
#pragma unroll
        for (int i = 0; i < 4; i++)
#pragma unroll
            for (int j = 0; j < 4; j++) s[i][j] = 0.0f;

#pragma unroll 8
        for (int d = 0; d < 64; d++) {
            float4 qv = *(const float4*)&Qs[d][ty * 4];
            float4 kv = *(const float4*)&KP[d][tx * 4];
            s[0][0] += qv.x * kv.x; s[0][1] += qv.x * kv.y; s[0][2] += qv.x * kv.z; s[0][3] += qv.x * kv.w;
            s[1][0] += qv.y * kv.x; s[1][1] += qv.y * kv.y; s[1][2] += qv.y * kv.z; s[1][3] += qv.y * kv.w;
            s[2][0] += qv.z * kv.x; s[2][1] += qv.z * kv.y; s[2][2] += qv.z * kv.z; s[2][3] += qv.z * kv.w;
            s[3][0] += qv.w * kv.x; s[3][1] += qv.w * kv.y; s[3][2] += qv.w * kv.z; s[3][3] += qv.w * kv.w;
        }

        // Per-row chunk max, reduced across the 16 lanes sharing ty
        float cm[4];
#pragma unroll
        for (int i = 0; i < 4; i++) {
            cm[i] = fmaxf(fmaxf(s[i][0], s[i][1]), fmaxf(s[i][2], s[i][3]));
#pragma unroll
            for (int off = 1; off < 16; off <<= 1)
                cm[i] = fmaxf(cm[i], __shfl_xor_sync(0xffffffffu, cm[i], off));
        }

        // Online rescale
#pragma unroll
        for (int i = 0; i < 4; i++) {
            float nm = fmaxf(m[i], cm[i]);
            float cz = __expf(m[i] - nm);
            float cw = g2 ? cz * cz : __expf(gam * (m[i] - nm));
            Z[i] *= cz; S2[i] *= cw; m[i] = nm;
#pragma unroll
            for (int j = 0; j < 4; j++) O[i][j] *= cw;
        }

        // Weights
        float w[4][4];
#pragma unroll
        for (int i = 0; i < 4; i++)
#pragma unroll
            for (int j = 0; j < 4; j++) {
                float x  = s[i][j] - m[i];
                float e1 = __expf(x);
                Z[i] += e1;
                float wv = g2 ? e1 * e1 : __expf(gam * x);
                S2[i] += wv;
                w[i][j] = wv;
            }

        __syncthreads();  // done reading KP as K

        // Store P into KP as [k][q] with XOR-swizzled float4 columns
#pragma unroll
        for (int j = 0; j < 4; j++) {
            int k  = tx * 4 + j;
            int c4 = (ty ^ (k & 15)) * 4;
            float4 pv = make_float4(w[0][j], w[1][j], w[2][j], w[3][j]);
            *(float4*)&KP[k][c4] = pv;
        }
        __syncthreads();

        // O += P V
#pragma unroll 8
        for (int k = 0; k < 64; k++) {
            int c4 = (ty ^ (k & 15)) * 4;
            float4 p = *(const float4*)&KP[k][c4];
            float4 v = *(const float4*)&Vs[k][tx * 4];
            O[0][0] += p.x * v.x; O[0][1] += p.x * v.y; O[0][2] += p.x * v.z; O[0][3] += p.x * v.w;
            O[1][0] += p.y * v.x; O[1][1] += p.y * v.y; O[1][2] += p.y * v.z; O[1][3] += p.y * v.w;
            O[2][0] += p.z * v.x; O[2][1] += p.z * v.y; O[2][2] += p.z * v.z; O[2][3] += p.z * v.w;
            O[3][0] += p.w * v.x; O[3][1] += p.w * v.y; O[3][2] += p.w * v.z; O[3][3] += p.w * v.w;
        }
        __syncthreads();  // before next stage overwrites KP/Vs
    }

    // Reduce Z, S2 across the 16-lane row group
#pragma unroll
    for (int i = 0; i < 4; i++) {
#pragma unroll
        for (int off = 1; off < 16; off <<= 1) {
            Z[i]  += __shfl_xor_sync(0xffffffffu, Z[i],  off);
            S2[i] += __shfl_xor_sync(0xffffffffu, S2[i], off);
        }
    }

    // Final scale + write to attention output [b*n][dim]
    const int b = bh >> 4, h = bh & 15;
#pragma unroll
    for (int i = 0; i < 4; i++) {
        float Zg = g2 ? Z[i] * Z[i] : __powf(Z[i], gam);
        float denom = alpha * S2[i] + 1e-6f * Zg;
        float sc = alpha / denom;
        float4 o = make_float4(O[i][0] * sc, O[i][1] * sc, O[i][2] * sc, O[i][3] * sc);
        int r = (b * NSEQ + q0 + ty * 4 + i) * DIM_ + h * HD_ + tx * 4;
        *(float4*)&g_AO[r] = o;
    }
}

// ---------------------------------------------------------------------------
extern "C" void kernel_launch(void* const* d_in, const int* in_sizes, int n_in,
                              void* d_out, int out_size)
{
    // Identify inputs by element count (robust to metadata ordering);
    // the two size-1 scalars keep their relative order: alpha then gamma.
    const float* x = nullptr, *Wqkv = nullptr, *bqkv = nullptr;
    const float* Wproj = nullptr, *bproj = nullptr, *fa = nullptr, *fg = nullptr;
    for (int i = 0; i < n_in; i++) {
        int sz = in_sizes[i];
        const float* p = (const float*)d_in[i];
        if      (sz == B_*NSEQ*DIM_)   x = p;
        else if (sz == 3*DIM_*DIM_)    Wqkv = p;
        else if (sz == 3*DIM_)         bqkv = p;
        else if (sz == DIM_*DIM_)      Wproj = p;
        else if (sz == DIM_)           bproj = p;
        else if (sz == 1)              { if (!fa) fa = p; else fg = p; }
    }

    float* out = (float*)d_out;

    // 1) Fused QKV projection, scatter into Q (scaled) / K^T / V
    gemm_kernel<0><<<dim3(3*DIM_/128, B_*NSEQ/128), 256>>>(x, Wqkv, bqkv, nullptr,
                                                           B_*NSEQ, 3*DIM_, DIM_);
    // 2) Focal flash attention -> g_AO
    flash_kernel<<<dim3(NSEQ/64, B_*H_), 256>>>(fa, fg);
    // 3) Output projection
    gemm_kernel<1><<<dim3(DIM_/128, B_*NSEQ/128), 256>>>(nullptr, Wproj, bproj, out,
                                                         B_*NSEQ, DIM_, DIM_);
}

// round 4
// speedup vs baseline: 2.0347x; 2.0347x over previous
#include <cuda_runtime.h>
#include <cstdint>

// Problem constants
#define B_    2
#define NSEQ  2048
#define DIM_  1024
#define H_    16
#define HD_   64
#define SCALE_F 0.125f   // HD^-0.5

// Scratch (device globals: allocation-free contract)
__device__ __align__(16) float g_Q [B_*H_*NSEQ*HD_];   // [bh][n][d], pre-scaled
__device__ __align__(16) float g_K [B_*H_*NSEQ*HD_];   // [bh][n][d]
__device__ __align__(16) float g_V [B_*H_*NSEQ*HD_];   // [bh][n][d]
__device__ __align__(16) float g_AO[B_*NSEQ*DIM_];     // attention out [b*n][dim]

// ---------------------------------------------------------------------------
// bf16x2 split helpers.  hi = top 16 bits of fp32 (exact bf16 truncation),
// lo = x - hi, truncated to bf16.  A*B ~= Ah*Bh + Ah*Bl + Al*Bh, err ~2^-15.
// Packed register layout: low 16 bits = element k, high 16 = element k+1.
// ---------------------------------------------------------------------------
__device__ __forceinline__ uint32_t packhi2(float x, float y) {
    return __byte_perm(__float_as_uint(x), __float_as_uint(y), 0x7632);
}
__device__ __forceinline__ uint32_t packlo2(float x, float y) {
    float lx = x - __uint_as_float(__float_as_uint(x) & 0xffff0000u);
    float ly = y - __uint_as_float(__float_as_uint(y) & 0xffff0000u);
    return __byte_perm(__float_as_uint(lx), __float_as_uint(ly), 0x7632);
}
// Split float4 (4 consecutive k of one row) -> 2 hi words + 2 lo words
__device__ __forceinline__ void split4(float4 v, uint32_t* hi, uint32_t* lo) {
    hi[0] = packhi2(v.x, v.y); hi[1] = packhi2(v.z, v.w);
    lo[0] = packlo2(v.x, v.y); lo[1] = packlo2(v.z, v.w);
}

// mma.sync m16n8k16 bf16: A row-major frag {a0..a3}, B col-major {b0,b1}, C fp32.
// A: a0=(g,2tg:2tg+1) a1=(g+8,..) a2=(g,2tg+8:+9) a3=(g+8,..)  [g=lane>>2,tg=lane&3]
// B: b0=(k=2tg:2tg+1, n=g) b1=(k=2tg+8:+9, n=g)
// C: c0=(g,2tg) c1=(g,2tg+1) c2=(g+8,2tg) c3=(g+8,2tg+1)
__device__ __forceinline__ void mma16(float* c, const uint32_t* a, const uint32_t* b) {
    asm("mma.sync.aligned.m16n8k16.row.col.f32.bf16.bf16.f32 "
        "{%0,%1,%2,%3}, {%4,%5,%6,%7}, {%8,%9}, {%0,%1,%2,%3};"
        : "+f"(c[0]), "+f"(c[1]), "+f"(c[2]), "+f"(c[3])
        : "r"(a[0]), "r"(a[1]), "r"(a[2]), "r"(a[3]), "r"(b[0]), "r"(b[1]));
}

// ---------------------------------------------------------------------------
// Split-bf16 GEMM: C[4096, Ncols] = A[4096,1024] @ W[Ncols,1024]^T + bias
// CTA 128x128, 256 thr (8 warps 2x4, warp tile 64x32), BK=32.
// Smem: packed-bf16 hi/lo tiles, stride 20 words (16 data + 4 pad):
//   frag bank = (20g+tg) mod 32 -> all 32 lanes distinct.
// MODE 0: QKV scatter.  MODE 1: plain store (input = g_AO).
// ---------------------------------------------------------------------------
#define GST 20
#define OFF_AHI 0
#define OFF_ALO (128*GST)
#define OFF_BHI (2*128*GST)
#define OFF_BLO (3*128*GST)
#define GEMM_SMEM (4*128*GST*4)   // 40960 B

template<int MODE>
__global__ __launch_bounds__(256)
void tc_gemm(const float* __restrict__ Ain, const float* __restrict__ W,
             const float* __restrict__ bias, float* __restrict__ C)
{
    extern __shared__ __align__(16) uint32_t smu[];
    const float* A = (MODE == 1) ? (const float*)g_AO : Ain;

    const int tid = threadIdx.x;
    const int wid = tid >> 5, lane = tid & 31;
    const int g = lane >> 2, tg = lane & 3;
    const int wm = wid >> 2, wn = wid & 3;
    const int row0 = blockIdx.y * 128, col0 = blockIdx.x * 128;

    float c[4][4][4];
#pragma unroll
    for (int mt = 0; mt < 4; mt++)
#pragma unroll
        for (int nt = 0; nt < 4; nt++) {
            c[mt][nt][0] = 0.f; c[mt][nt][1] = 0.f; c[mt][nt][2] = 0.f; c[mt][nt][3] = 0.f;
        }

    // LDG assignment: thread covers row lr, 16 floats (half lhalf) per tile
    const int lr = tid >> 1, lhalf = tid & 1;
    float4 a4[4], b4[4];
    auto ldg = [&](int ch) {
        const float* ap = A + (size_t)(row0 + lr) * DIM_ + ch * 32 + lhalf * 16;
        const float* bp = W + (size_t)(col0 + lr) * DIM_ + ch * 32 + lhalf * 16;
#pragma unroll
        for (int j = 0; j < 4; j++) {
            a4[j] = *(const float4*)(ap + 4 * j);
            b4[j] = *(const float4*)(bp + 4 * j);
        }
    };
    ldg(0);

    for (int ch = 0; ch < 32; ch++) {
        __syncthreads();   // prior compute done -> safe to overwrite smem
#pragma unroll
        for (int j = 0; j < 4; j++) {
            uint32_t hi[2], lo[2];
            int k2 = lhalf * 8 + 2 * j;
            split4(a4[j], hi, lo);
            *(uint2*)&smu[OFF_AHI + lr * GST + k2] = make_uint2(hi[0], hi[1]);
            *(uint2*)&smu[OFF_ALO + lr * GST + k2] = make_uint2(lo[0], lo[1]);
            split4(b4[j], hi, lo);
            *(uint2*)&smu[OFF_BHI + lr * GST + k2] = make_uint2(hi[0], hi[1]);
            *(uint2*)&smu[OFF_BLO + lr * GST + k2] = make_uint2(lo[0], lo[1]);
        }
        __syncthreads();
        if (ch < 31) ldg(ch + 1);

#pragma unroll
        for (int ks = 0; ks < 2; ks++) {
            const int kb = ks * 8;
            uint32_t ah[4][4], al[4][4];
#pragma unroll
            for (int mt = 0; mt < 4; mt++) {
                int r = wm * 64 + mt * 16 + g;
                ah[mt][0] = smu[OFF_AHI + r * GST + kb + tg];
                ah[mt][1] = smu[OFF_AHI + (r + 8) * GST + kb + tg];
                ah[mt][2] = smu[OFF_AHI + r * GST + kb + 4 + tg];
                ah[mt][3] = smu[OFF_AHI + (r + 8) * GST + kb + 4 + tg];
                al[mt][0] = smu[OFF_ALO + r * GST + kb + tg];
                al[mt][1] = smu[OFF_ALO + (r + 8) * GST + kb + tg];
                al[mt][2] = smu[OFF_ALO + r * GST + kb + 4 + tg];
                al[mt][3] = smu[OFF_ALO + (r + 8) * GST + kb + 4 + tg];
            }
#pragma unroll
            for (int nt = 0; nt < 4; nt++) {
                int rn = wn * 32 + nt * 8 + g;
                uint32_t bh[2], bl[2];
                bh[0] = smu[OFF_BHI + rn * GST + kb + tg];
                bh[1] = smu[OFF_BHI + rn * GST + kb + 4 + tg];
                bl[0] = smu[OFF_BLO + rn * GST + kb + tg];
                bl[1] = smu[OFF_BLO + rn * GST + kb + 4 + tg];
#pragma unroll
                for (int mt = 0; mt < 4; mt++) {
                    mma16(c[mt][nt], ah[mt], bh);
                    mma16(c[mt][nt], ah[mt], bl);
                    mma16(c[mt][nt], al[mt], bh);
                }
            }
        }
    }

    // Epilogue: direct float2 stores
#pragma unroll
    for (int mt = 0; mt < 4; mt++) {
#pragma unroll
        for (int half = 0; half < 2; half++) {
            int row = row0 + wm * 64 + mt * 16 + g + half * 8;
#pragma unroll
            for (int nt = 0; nt < 4; nt++) {
                int col = col0 + wn * 32 + nt * 8 + 2 * tg;
                float v0 = c[mt][nt][half * 2 + 0] + bias[col];
                float v1 = c[mt][nt][half * 2 + 1] + bias[col + 1];
                if (MODE == 1) {
                    *(float2*)&C[(size_t)row * DIM_ + col] = make_float2(v0, v1);
                } else {
                    int b = row >> 11, n = row & (NSEQ - 1);
                    int which = col >> 10, rem = col & 1023;
                    int h = rem >> 6, d = rem & 63;
                    size_t idx = (((size_t)(b * H_ + h)) * NSEQ + n) * HD_ + d;
                    if (which == 0)
                        *(float2*)&g_Q[idx] = make_float2(v0 * SCALE_F, v1 * SCALE_F);
                    else if (which == 1)
                        *(float2*)&g_K[idx] = make_float2(v0, v1);
                    else
                        *(float2*)&g_V[idx] = make_float2(v0, v1);
                }
            }
        }
    }
}

// ---------------------------------------------------------------------------
// Flash focal attention, split-bf16 mma.
// 256 thr / 8 warps, q-block 128 (16 rows/warp), key chunks of 64.
// Smem (uint32 words): Qhi/Qlo [128][36] (k2 of d), Phi/Plo [128][36] (k2 of key),
// Khi/Klo [64][36] (key rows, k2 of d), Vhi/Vlo [32][72] (k2 of key rows, d cols).
// Bank maps: Q/K/P frag = 4g+tg (distinct), V frag = 8tg+g (distinct).
// ---------------------------------------------------------------------------
#define FQ_HI 0
#define FQ_LO (128*36)
#define FP_HI (2*128*36)
#define FP_LO (3*128*36)
#define FK_HI (4*128*36)
#define FK_LO (4*128*36 + 64*36)
#define FV_HI (4*128*36 + 2*64*36)
#define FV_LO (4*128*36 + 2*64*36 + 32*72)
#define FLASH_WORDS (4*128*36 + 2*64*36 + 2*32*72)
#define FLASH_SMEM (FLASH_WORDS*4)   // 110592 B

__global__ __launch_bounds__(256)
void flash_kernel(const float* __restrict__ falpha, const float* __restrict__ fgamma)
{
    extern __shared__ __align__(16) uint32_t smu[];
    const int tid = threadIdx.x, wid = tid >> 5, lane = tid & 31;
    const int g = lane >> 2, tg = lane & 3;
    const int bh = blockIdx.y, q0 = blockIdx.x * 128;
    const int qb = wid * 16;

    const float gam = fgamma[0], alpha = falpha[0];
    const bool g2 = (gam == 2.0f);

    const float* Qg = g_Q + ((size_t)bh * NSEQ + q0) * HD_;
    const float* Kg = g_K + (size_t)bh * NSEQ * HD_;
    const float* Vg = g_V + (size_t)bh * NSEQ * HD_;

    // ---- Q tile: load + split + store packed (once) ----
    {
        int r = tid >> 1, half = tid & 1;
        const float* qp = Qg + (size_t)r * HD_ + half * 32;
#pragma unroll
        for (int j = 0; j < 8; j++) {
            float4 v = *(const float4*)(qp + 4 * j);
            uint32_t hi[2], lo[2];
            split4(v, hi, lo);
            int k2 = half * 16 + 2 * j;
            *(uint2*)&smu[FQ_HI + r * 36 + k2] = make_uint2(hi[0], hi[1]);
            *(uint2*)&smu[FQ_LO + r * 36 + k2] = make_uint2(lo[0], lo[1]);
        }
    }

    // KV LDG staging (registers)
    const int kr = tid >> 2, kq4 = tid & 3;        // K: row kr, 16 floats
    const int vp = tid >> 3, vc8 = tid & 7;        // V: row pair 2vp/2vp+1, 8 cols
    float4 kv4[4], va[2], vb[2];
    auto ldgKV = [&](int ch) {
        const float* kp = Kg + (size_t)(ch * 64 + kr) * HD_ + kq4 * 16;
#pragma unroll
        for (int j = 0; j < 4; j++) kv4[j] = *(const float4*)(kp + 4 * j);
        const float* vpa = Vg + (size_t)(ch * 64 + 2 * vp) * HD_ + vc8 * 8;
        const float* vpb = vpa + HD_;
        va[0] = *(const float4*)(vpa);  va[1] = *(const float4*)(vpa + 4);
        vb[0] = *(const float4*)(vpb);  vb[1] = *(const float4*)(vpb + 4);
    };
    ldgKV(0);

    float o[8][4];
#pragma unroll
    for (int nt = 0; nt < 8; nt++) { o[nt][0] = o[nt][1] = o[nt][2] = o[nt][3] = 0.f; }
    float m0 = -1e30f, m1 = -1e30f, Z0 = 0.f, Z1 = 0.f, S20 = 0.f, S21 = 0.f;

    for (int ch = 0; ch < 32; ch++) {
        __syncthreads();   // prior chunk compute done
        // ---- STS K (row-pairs along d) ----
#pragma unroll
        for (int j = 0; j < 4; j++) {
            uint32_t hi[2], lo[2];
            split4(kv4[j], hi, lo);
            int k2 = kq4 * 8 + 2 * j;
            *(uint2*)&smu[FK_HI + kr * 36 + k2] = make_uint2(hi[0], hi[1]);
            *(uint2*)&smu[FK_LO + kr * 36 + k2] = make_uint2(lo[0], lo[1]);
        }
        // ---- STS V (pairs across rows: word(k2,d) = {V[2k2][d], V[2k2+1][d]}) ----
        {
            uint32_t hi[8], lo[8];
            float* fa = (float*)va; float* fb = (float*)vb;
#pragma unroll
            for (int j = 0; j < 8; j++) {
                hi[j] = packhi2(fa[j], fb[j]);
                lo[j] = packlo2(fa[j], fb[j]);
            }
            uint32_t base = vp * 72 + vc8 * 8;
            *(uint4*)&smu[FV_HI + base]     = *(uint4*)&hi[0];
            *(uint4*)&smu[FV_HI + base + 4] = *(uint4*)&hi[4];
            *(uint4*)&smu[FV_LO + base]     = *(uint4*)&lo[0];
            *(uint4*)&smu[FV_LO + base + 4] = *(uint4*)&lo[4];
        }
        __syncthreads();
        if (ch < 31) ldgKV(ch + 1);

        // ---- S = Q K^T ----
        float s[8][4];
#pragma unroll
        for (int nt = 0; nt < 8; nt++) { s[nt][0] = s[nt][1] = s[nt][2] = s[nt][3] = 0.f; }
#pragma unroll
        for (int ks = 0; ks < 4; ks++) {
            const int kb = ks * 8;
            uint32_t ah[4], al[4];
            ah[0] = smu[FQ_HI + (qb + g) * 36 + kb + tg];
            ah[1] = smu[FQ_HI + (qb + g + 8) * 36 + kb + tg];
            ah[2] = smu[FQ_HI + (qb + g) * 36 + kb + 4 + tg];
            ah[3] = smu[FQ_HI + (qb + g + 8) * 36 + kb + 4 + tg];
            al[0] = smu[FQ_LO + (qb + g) * 36 + kb + tg];
            al[1] = smu[FQ_LO + (qb + g + 8) * 36 + kb + tg];
            al[2] = smu[FQ_LO + (qb + g) * 36 + kb + 4 + tg];
            al[3] = smu[FQ_LO + (qb + g + 8) * 36 + kb + 4 + tg];
#pragma unroll
            for (int nt = 0; nt < 8; nt++) {
                int rn = nt * 8 + g;
                uint32_t bhh[2], bll[2];
                bhh[0] = smu[FK_HI + rn * 36 + kb + tg];
                bhh[1] = smu[FK_HI + rn * 36 + kb + 4 + tg];
                bll[0] = smu[FK_LO + rn * 36 + kb + tg];
                bll[1] = smu[FK_LO + rn * 36 + kb + 4 + tg];
                mma16(s[nt], ah, bhh);
                mma16(s[nt], ah, bll);
                mma16(s[nt], al, bhh);
            }
        }

        // ---- chunk max per row (quad reduce) ----
        float cm0 = -1e30f, cm1 = -1e30f;
#pragma unroll
        for (int nt = 0; nt < 8; nt++) {
            cm0 = fmaxf(cm0, fmaxf(s[nt][0], s[nt][1]));
            cm1 = fmaxf(cm1, fmaxf(s[nt][2], s[nt][3]));
        }
        cm0 = fmaxf(cm0, __shfl_xor_sync(0xffffffffu, cm0, 1));
        cm0 = fmaxf(cm0, __shfl_xor_sync(0xffffffffu, cm0, 2));
        cm1 = fmaxf(cm1, __shfl_xor_sync(0xffffffffu, cm1, 1));
        cm1 = fmaxf(cm1, __shfl_xor_sync(0xffffffffu, cm1, 2));

        // ---- online rescale ----
        float nm0 = fmaxf(m0, cm0), nm1 = fmaxf(m1, cm1);
        float cz0 = __expf(m0 - nm0), cz1 = __expf(m1 - nm1);
        float cw0 = g2 ? cz0 * cz0 : __expf(gam * (m0 - nm0));
        float cw1 = g2 ? cz1 * cz1 : __expf(gam * (m1 - nm1));
        Z0 *= cz0; Z1 *= cz1; S20 *= cw0; S21 *= cw1; m0 = nm0; m1 = nm1;
#pragma unroll
        for (int nt = 0; nt < 8; nt++) {
            o[nt][0] *= cw0; o[nt][1] *= cw0; o[nt][2] *= cw1; o[nt][3] *= cw1;
        }

        // ---- weights + packed P store (warp-private rows) ----
        float zp0 = 0.f, zp1 = 0.f, wp0 = 0.f, wp1 = 0.f;
#pragma unroll
        for (int nt = 0; nt < 8; nt++) {
            float e0 = __expf(s[nt][0] - m0), e1 = __expf(s[nt][1] - m0);
            float e2 = __expf(s[nt][2] - m1), e3 = __expf(s[nt][3] - m1);
            zp0 += e0 + e1; zp1 += e2 + e3;
            float w0, w1, w2, w3;
            if (g2) { w0 = e0 * e0; w1 = e1 * e1; w2 = e2 * e2; w3 = e3 * e3; }
            else {
                w0 = __expf(gam * (s[nt][0] - m0)); w1 = __expf(gam * (s[nt][1] - m0));
                w2 = __expf(gam * (s[nt][2] - m1)); w3 = __expf(gam * (s[nt][3] - m1));
            }
            wp0 += w0 + w1; wp1 += w2 + w3;
            int k2 = nt * 4 + tg;
            smu[FP_HI + (qb + g) * 36 + k2]     = packhi2(w0, w1);
            smu[FP_LO + (qb + g) * 36 + k2]     = packlo2(w0, w1);
            smu[FP_HI + (qb + g + 8) * 36 + k2] = packhi2(w2, w3);
            smu[FP_LO + (qb + g + 8) * 36 + k2] = packlo2(w2, w3);
        }
        Z0 += zp0; Z1 += zp1; S20 += wp0; S21 += wp1;
        __syncwarp();

        // ---- O += P V ----
#pragma unroll
        for (int ks = 0; ks < 4; ks++) {
            const int kb = ks * 8;
            uint32_t ah[4], al[4];
            ah[0] = smu[FP_HI + (qb + g) * 36 + kb + tg];
            ah[1] = smu[FP_HI + (qb + g + 8) * 36 + kb + tg];
            ah[2] = smu[FP_HI + (qb + g) * 36 + kb + 4 + tg];
            ah[3] = smu[FP_HI + (qb + g + 8) * 36 + kb + 4 + tg];
            al[0] = smu[FP_LO + (qb + g) * 36 + kb + tg];
            al[1] = smu[FP_LO + (qb + g + 8) * 36 + kb + tg];
            al[2] = smu[FP_LO + (qb + g) * 36 + kb + 4 + tg];
            al[3] = smu[FP_LO + (qb + g + 8) * 36 + kb + 4 + tg];
#pragma unroll
            for (int nt = 0; nt < 8; nt++) {
                int dn = nt * 8 + g;
                uint32_t bhh[2], bll[2];
                bhh[0] = smu[FV_HI + (kb + tg) * 72 + dn];
                bhh[1] = smu[FV_HI + (kb + 4 + tg) * 72 + dn];
                bll[0] = smu[FV_LO + (kb + tg) * 72 + dn];
                bll[1] = smu[FV_LO + (kb + 4 + tg) * 72 + dn];
                mma16(o[nt], ah, bhh);
                mma16(o[nt], ah, bll);
                mma16(o[nt], al, bhh);
            }
        }
    }

    // ---- final reduce + write ----
    Z0  += __shfl_xor_sync(0xffffffffu, Z0, 1);  Z0  += __shfl_xor_sync(0xffffffffu, Z0, 2);
    Z1  += __shfl_xor_sync(0xffffffffu, Z1, 1);  Z1  += __shfl_xor_sync(0xffffffffu, Z1, 2);
    S20 += __shfl_xor_sync(0xffffffffu, S20, 1); S20 += __shfl_xor_sync(0xffffffffu, S20, 2);
    S21 += __shfl_xor_sync(0xffffffffu, S21, 1); S21 += __shfl_xor_sync(0xffffffffu, S21, 2);

    float Zg0 = g2 ? Z0 * Z0 : __powf(Z0, gam);
    float Zg1 = g2 ? Z1 * Z1 : __powf(Z1, gam);
    float sc0 = alpha / (alpha * S20 + 1e-6f * Zg0);
    float sc1 = alpha / (alpha * S21 + 1e-6f * Zg1);

    const int b = bh >> 4, h = bh & 15;
    const int qA = q0 + qb + g, qB = qA + 8;
#pragma unroll
    for (int nt = 0; nt < 8; nt++) {
        int d = nt * 8 + 2 * tg;
        *(float2*)&g_AO[((size_t)b * NSEQ + qA) * DIM_ + h * HD_ + d] =
            make_float2(o[nt][0] * sc0, o[nt][1] * sc0);
        *(float2*)&g_AO[((size_t)b * NSEQ + qB) * DIM_ + h * HD_ + d] =
            make_float2(o[nt][2] * sc1, o[nt][3] * sc1);
    }
}

// ---------------------------------------------------------------------------
extern "C" void kernel_launch(void* const* d_in, const int* in_sizes, int n_in,
                              void* d_out, int out_size)
{
    const float* x = nullptr, *Wqkv = nullptr, *bqkv = nullptr;
    const float* Wproj = nullptr, *bproj = nullptr, *fa = nullptr, *fg = nullptr;
    for (int i = 0; i < n_in; i++) {
        int sz = in_sizes[i];
        const float* p = (const float*)d_in[i];
        if      (sz == B_*NSEQ*DIM_)   x = p;
        else if (sz == 3*DIM_*DIM_)    Wqkv = p;
        else if (sz == 3*DIM_)         bqkv = p;
        else if (sz == DIM_*DIM_)      Wproj = p;
        else if (sz == DIM_)           bproj = p;
        else if (sz == 1)              { if (!fa) fa = p; else fg = p; }
    }
    float* out = (float*)d_out;

    cudaFuncSetAttribute(tc_gemm<0>,   cudaFuncAttributeMaxDynamicSharedMemorySize, GEMM_SMEM);
    cudaFuncSetAttribute(tc_gemm<1>,   cudaFuncAttributeMaxDynamicSharedMemorySize, GEMM_SMEM);
    cudaFuncSetAttribute(flash_kernel, cudaFuncAttributeMaxDynamicSharedMemorySize, FLASH_SMEM);

    // 1) Fused QKV projection -> Q(scaled)/K/V
    tc_gemm<0><<<dim3(3*DIM_/128, (B_*NSEQ)/128), 256, GEMM_SMEM>>>(x, Wqkv, bqkv, nullptr);
    // 2) Focal flash attention -> g_AO
    flash_kernel<<<dim3(NSEQ/128, B_*H_), 256, FLASH_SMEM>>>(fa, fg);
    // 3) Output projection
    tc_gemm<1><<<dim3(DIM_/128, (B_*NSEQ)/128), 256, GEMM_SMEM>>>(nullptr, Wproj, bproj, out);
}

// round 5
// speedup vs baseline: 2.3080x; 1.1343x over previous
#include <cuda_runtime.h>
#include <cstdint>

// Problem constants
#define B_    2
#define NSEQ  2048
#define DIM_  1024
#define H_    16
#define HD_   64
#define SCALE_F 0.125f   // HD^-0.5

// Scratch (device globals: allocation-free contract)
__device__ __align__(16) float g_Q [B_*H_*NSEQ*HD_];   // [bh][n][d], pre-scaled
__device__ __align__(16) float g_K [B_*H_*NSEQ*HD_];   // [bh][n][d]
__device__ __align__(16) float g_V [B_*H_*NSEQ*HD_];   // [bh][n][d]
__device__ __align__(16) float g_AO[B_*NSEQ*DIM_];     // attention out [b*n][dim]

// ---------------------------------------------------------------------------
// bf16x2 split helpers: hi = top16(fp32), lo = bf16(x - hi). 3-mma split.
// ---------------------------------------------------------------------------
__device__ __forceinline__ uint32_t packhi2(float x, float y) {
    return __byte_perm(__float_as_uint(x), __float_as_uint(y), 0x7632);
}
__device__ __forceinline__ uint32_t packlo2(float x, float y) {
    float lx = x - __uint_as_float(__float_as_uint(x) & 0xffff0000u);
    float ly = y - __uint_as_float(__float_as_uint(y) & 0xffff0000u);
    return __byte_perm(__float_as_uint(lx), __float_as_uint(ly), 0x7632);
}
__device__ __forceinline__ void split4(float4 v, uint32_t* hi, uint32_t* lo) {
    hi[0] = packhi2(v.x, v.y); hi[1] = packhi2(v.z, v.w);
    lo[0] = packlo2(v.x, v.y); lo[1] = packlo2(v.z, v.w);
}
__device__ __forceinline__ uint32_t smem_u32(const void* p) {
    uint32_t a;
    asm("{ .reg .u64 t; cvta.to.shared.u64 t, %1; cvt.u32.u64 %0, t; }" : "=r"(a) : "l"(p));
    return a;
}
__device__ __forceinline__ void mma16(float* c, const uint32_t* a, const uint32_t* b) {
    asm("mma.sync.aligned.m16n8k16.row.col.f32.bf16.bf16.f32 "
        "{%0,%1,%2,%3}, {%4,%5,%6,%7}, {%8,%9}, {%0,%1,%2,%3};"
        : "+f"(c[0]), "+f"(c[1]), "+f"(c[2]), "+f"(c[3])
        : "r"(a[0]), "r"(a[1]), "r"(a[2]), "r"(a[3]), "r"(b[0]), "r"(b[1]));
}
__device__ __forceinline__ void ldmx4(uint32_t* r, uint32_t a) {
    asm volatile("ldmatrix.sync.aligned.m8n8.x4.shared.b16 {%0,%1,%2,%3}, [%4];"
        : "=r"(r[0]), "=r"(r[1]), "=r"(r[2]), "=r"(r[3]) : "r"(a));
}
__device__ __forceinline__ void ldmx4t(uint32_t* r, uint32_t a) {
    asm volatile("ldmatrix.sync.aligned.m8n8.x4.trans.shared.b16 {%0,%1,%2,%3}, [%4];"
        : "=r"(r[0]), "=r"(r[1]), "=r"(r[2]), "=r"(r[3]) : "r"(a));
}

// ---------------------------------------------------------------------------
// Split-bf16 GEMM: C[4096, Ncols] = A @ W^T + bias.  CTA 128x128, 8 warps
// (2x4, warp 64x32), BK=32, DOUBLE-BUFFERED smem, ldmatrix fragment loads.
// Smem word layout per buffer: [AHI][ALO][BHI][BLO], each [128][20].
// ---------------------------------------------------------------------------
#define GST 20
#define GARR (128*GST)        // 2560 words
#define GBUF (4*GARR)         // 10240 words per buffer
#define GEMM_SMEM (2*GBUF*4)  // 81920 B

template<int MODE>
__global__ __launch_bounds__(256)
void tc_gemm(const float* __restrict__ Ain, const float* __restrict__ W,
             const float* __restrict__ bias, float* __restrict__ C)
{
    extern __shared__ __align__(16) uint32_t smu[];
    const uint32_t sb = smem_u32(smu);
    const float* A = (MODE == 1) ? (const float*)g_AO : Ain;

    const int tid = threadIdx.x;
    const int wid = tid >> 5, lane = tid & 31;
    const int g = lane >> 2, tg = lane & 3;
    const int wm = wid >> 2, wn = wid & 3;
    const int row0 = blockIdx.y * 128, col0 = blockIdx.x * 128;

    // ldmatrix per-lane address components (word units)
    const int rA = wm * 64 + (lane & 15);
    const int kA = (lane >> 4) * 4;
    const int rB = wn * 32 + (lane & 7) + ((lane >> 4) << 3);
    const int kB = ((lane >> 3) & 1) * 4;

    float c[4][4][4];
#pragma unroll
    for (int mt = 0; mt < 4; mt++)
#pragma unroll
        for (int nt = 0; nt < 4; nt++) {
            c[mt][nt][0] = 0.f; c[mt][nt][1] = 0.f; c[mt][nt][2] = 0.f; c[mt][nt][3] = 0.f;
        }

    const int lr = tid >> 1, lhalf = tid & 1;
    float4 a4[4], b4[4];
    auto ldg = [&](int ch) {
        const float* ap = A + (size_t)(row0 + lr) * DIM_ + ch * 32 + lhalf * 16;
        const float* bp = W + (size_t)(col0 + lr) * DIM_ + ch * 32 + lhalf * 16;
#pragma unroll
        for (int j = 0; j < 4; j++) {
            a4[j] = *(const float4*)(ap + 4 * j);
            b4[j] = *(const float4*)(bp + 4 * j);
        }
    };
    auto sts = [&](int buf) {
        const int bo = buf * GBUF;
#pragma unroll
        for (int j = 0; j < 4; j++) {
            uint32_t hi[2], lo[2];
            int k2 = lhalf * 8 + 2 * j;
            split4(a4[j], hi, lo);
            *(uint2*)&smu[bo + lr * GST + k2]            = make_uint2(hi[0], hi[1]);
            *(uint2*)&smu[bo + GARR + lr * GST + k2]     = make_uint2(lo[0], lo[1]);
            split4(b4[j], hi, lo);
            *(uint2*)&smu[bo + 2 * GARR + lr * GST + k2] = make_uint2(hi[0], hi[1]);
            *(uint2*)&smu[bo + 3 * GARR + lr * GST + k2] = make_uint2(lo[0], lo[1]);
        }
    };

    ldg(0); sts(0);
    __syncthreads();

    for (int ch = 0; ch < 32; ch++) {
        if (ch < 31) ldg(ch + 1);
        const uint32_t bo = sb + (uint32_t)(ch & 1) * (GBUF * 4);
#pragma unroll
        for (int ks = 0; ks < 2; ks++) {
            const int kb = ks * 8;
            uint32_t ah[4][4], al[4][4];
#pragma unroll
            for (int mt = 0; mt < 4; mt++) {
                ldmx4(ah[mt], bo + (uint32_t)((rA + mt * 16) * GST + kb + kA) * 4);
                ldmx4(al[mt], bo + (uint32_t)(GARR + (rA + mt * 16) * GST + kb + kA) * 4);
            }
            uint32_t bh[4][2], bl[4][2];
#pragma unroll
            for (int ntp = 0; ntp < 2; ntp++) {
                uint32_t t[4];
                ldmx4(t, bo + (uint32_t)(2 * GARR + (rB + ntp * 16) * GST + kb + kB) * 4);
                bh[2*ntp][0] = t[0]; bh[2*ntp][1] = t[1];
                bh[2*ntp+1][0] = t[2]; bh[2*ntp+1][1] = t[3];
                ldmx4(t, bo + (uint32_t)(3 * GARR + (rB + ntp * 16) * GST + kb + kB) * 4);
                bl[2*ntp][0] = t[0]; bl[2*ntp][1] = t[1];
                bl[2*ntp+1][0] = t[2]; bl[2*ntp+1][1] = t[3];
            }
#pragma unroll
            for (int nt = 0; nt < 4; nt++)
#pragma unroll
                for (int mt = 0; mt < 4; mt++) {
                    mma16(c[mt][nt], ah[mt], bh[nt]);
                    mma16(c[mt][nt], ah[mt], bl[nt]);
                    mma16(c[mt][nt], al[mt], bh[nt]);
                }
        }
        if (ch < 31) { sts((ch + 1) & 1); __syncthreads(); }
    }

    // Epilogue
#pragma unroll
    for (int mt = 0; mt < 4; mt++) {
#pragma unroll
        for (int half = 0; half < 2; half++) {
            int row = row0 + wm * 64 + mt * 16 + g + half * 8;
#pragma unroll
            for (int nt = 0; nt < 4; nt++) {
                int col = col0 + wn * 32 + nt * 8 + 2 * tg;
                float v0 = c[mt][nt][half * 2 + 0] + bias[col];
                float v1 = c[mt][nt][half * 2 + 1] + bias[col + 1];
                if (MODE == 1) {
                    *(float2*)&C[(size_t)row * DIM_ + col] = make_float2(v0, v1);
                } else {
                    int b = row >> 11, n = row & (NSEQ - 1);
                    int which = col >> 10, rem = col & 1023;
                    int h = rem >> 6, d = rem & 63;
                    size_t idx = (((size_t)(b * H_ + h)) * NSEQ + n) * HD_ + d;
                    if (which == 0)
                        *(float2*)&g_Q[idx] = make_float2(v0 * SCALE_F, v1 * SCALE_F);
                    else if (which == 1)
                        *(float2*)&g_K[idx] = make_float2(v0, v1);
                    else
                        *(float2*)&g_V[idx] = make_float2(v0, v1);
                }
            }
        }
    }
}

// ---------------------------------------------------------------------------
// Flash focal attention, split-bf16 + ldmatrix, double-buffered K/V.
// Smem word offsets: Q hi/lo [128][36], P hi/lo [128][36],
// K hi/lo [2][64][36], V hi/lo [2][64][36] (row-major keys, trans-ldmatrix).
// ---------------------------------------------------------------------------
#define FQH 0
#define FQL 4608
#define FPH 9216
#define FPL 13824
#define FKH 18432
#define FKL 23040
#define FVH 27648
#define FVL 32256
#define FKVB 2304                  // per-buffer stride (64*36)
#define FLASH_SMEM (36864*4)       // 147456 B

__global__ __launch_bounds__(256)
void flash_kernel(const float* __restrict__ falpha, const float* __restrict__ fgamma)
{
    extern __shared__ __align__(16) uint32_t smu[];
    const uint32_t sb = smem_u32(smu);
    const int tid = threadIdx.x, wid = tid >> 5, lane = tid & 31;
    const int g = lane >> 2, tg = lane & 3;
    const int bh = blockIdx.y, q0 = blockIdx.x * 128;
    const int qb = wid * 16;

    const float gam = fgamma[0], alpha = falpha[0];
    const bool g2 = (gam == 2.0f);

    const float* Qg = g_Q + ((size_t)bh * NSEQ + q0) * HD_;
    const float* Kg = g_K + (size_t)bh * NSEQ * HD_;
    const float* Vg = g_V + (size_t)bh * NSEQ * HD_;

    // ldmatrix per-lane address parts (word units)
    const int r16 = lane & 15;            // A/trans row select
    const int kA  = (lane >> 4) * 4;      // A/trans word-half
    const int rK  = (lane & 7) + ((lane >> 4) << 3);   // B rows (2 n-tiles)
    const int kB  = ((lane >> 3) & 1) * 4;

    // ---- Q tile: load + split + packed store (once) ----
    {
        int r = tid >> 1, half = tid & 1;
        const float* qp = Qg + (size_t)r * HD_ + half * 32;
#pragma unroll
        for (int j = 0; j < 8; j++) {
            float4 v = *(const float4*)(qp + 4 * j);
            uint32_t hi[2], lo[2];
            split4(v, hi, lo);
            int k2 = half * 16 + 2 * j;
            *(uint2*)&smu[FQH + r * 36 + k2] = make_uint2(hi[0], hi[1]);
            *(uint2*)&smu[FQL + r * 36 + k2] = make_uint2(lo[0], lo[1]);
        }
    }

    // K/V LDG staging (row-major, 64 rows x 64 f32 each)
    const int kr = tid >> 2, kq4 = tid & 3;
    float4 k4[4], v4[4];
    auto ldgKV = [&](int ch) {
        const float* kp = Kg + (size_t)(ch * 64 + kr) * HD_ + kq4 * 16;
        const float* vp = Vg + (size_t)(ch * 64 + kr) * HD_ + kq4 * 16;
#pragma unroll
        for (int j = 0; j < 4; j++) {
            k4[j] = *(const float4*)(kp + 4 * j);
            v4[j] = *(const float4*)(vp + 4 * j);
        }
    };
    auto stsKV = [&](int buf) {
        const int bo = buf * FKVB;
#pragma unroll
        for (int j = 0; j < 4; j++) {
            uint32_t hi[2], lo[2];
            int k2 = kq4 * 8 + 2 * j;
            split4(k4[j], hi, lo);
            *(uint2*)&smu[FKH + bo + kr * 36 + k2] = make_uint2(hi[0], hi[1]);
            *(uint2*)&smu[FKL + bo + kr * 36 + k2] = make_uint2(lo[0], lo[1]);
            split4(v4[j], hi, lo);
            *(uint2*)&smu[FVH + bo + kr * 36 + k2] = make_uint2(hi[0], hi[1]);
            *(uint2*)&smu[FVL + bo + kr * 36 + k2] = make_uint2(lo[0], lo[1]);
        }
    };

    ldgKV(0); stsKV(0);
    __syncthreads();

    float o[8][4];
#pragma unroll
    for (int nt = 0; nt < 8; nt++) { o[nt][0] = o[nt][1] = o[nt][2] = o[nt][3] = 0.f; }
    float m0 = -1e30f, m1 = -1e30f, Z0 = 0.f, Z1 = 0.f, S20 = 0.f, S21 = 0.f;

    for (int ch = 0; ch < 32; ch++) {
        if (ch < 31) ldgKV(ch + 1);
        const uint32_t bko = (uint32_t)(ch & 1) * FKVB;

        // ---- S = Q K^T ----
        float s[8][4];
#pragma unroll
        for (int nt = 0; nt < 8; nt++) { s[nt][0] = s[nt][1] = s[nt][2] = s[nt][3] = 0.f; }
#pragma unroll
        for (int ks = 0; ks < 4; ks++) {
            const int kb = ks * 8;
            uint32_t qh[4], ql[4];
            ldmx4(qh, sb + (uint32_t)(FQH + (qb + r16) * 36 + kb + kA) * 4);
            ldmx4(ql, sb + (uint32_t)(FQL + (qb + r16) * 36 + kb + kA) * 4);
#pragma unroll
            for (int ntp = 0; ntp < 4; ntp++) {
                uint32_t th[4], tl[4];
                ldmx4(th, sb + (uint32_t)(FKH + bko + (rK + ntp * 16) * 36 + kb + kB) * 4);
                ldmx4(tl, sb + (uint32_t)(FKL + bko + (rK + ntp * 16) * 36 + kb + kB) * 4);
                mma16(s[2*ntp],   qh, &th[0]); mma16(s[2*ntp],   qh, &tl[0]); mma16(s[2*ntp],   ql, &th[0]);
                mma16(s[2*ntp+1], qh, &th[2]); mma16(s[2*ntp+1], qh, &tl[2]); mma16(s[2*ntp+1], ql, &th[2]);
            }
        }

        // ---- chunk max per row (quad reduce) ----
        float cm0 = -1e30f, cm1 = -1e30f;
#pragma unroll
        for (int nt = 0; nt < 8; nt++) {
            cm0 = fmaxf(cm0, fmaxf(s[nt][0], s[nt][1]));
            cm1 = fmaxf(cm1, fmaxf(s[nt][2], s[nt][3]));
        }
        cm0 = fmaxf(cm0, __shfl_xor_sync(0xffffffffu, cm0, 1));
        cm0 = fmaxf(cm0, __shfl_xor_sync(0xffffffffu, cm0, 2));
        cm1 = fmaxf(cm1, __shfl_xor_sync(0xffffffffu, cm1, 1));
        cm1 = fmaxf(cm1, __shfl_xor_sync(0xffffffffu, cm1, 2));

        // ---- online rescale ----
        float nm0 = fmaxf(m0, cm0), nm1 = fmaxf(m1, cm1);
        float cz0 = __expf(m0 - nm0), cz1 = __expf(m1 - nm1);
        float cw0 = g2 ? cz0 * cz0 : __expf(gam * (m0 - nm0));
        float cw1 = g2 ? cz1 * cz1 : __expf(gam * (m1 - nm1));
        Z0 *= cz0; Z1 *= cz1; S20 *= cw0; S21 *= cw1; m0 = nm0; m1 = nm1;
#pragma unroll
        for (int nt = 0; nt < 8; nt++) {
            o[nt][0] *= cw0; o[nt][1] *= cw0; o[nt][2] *= cw1; o[nt][3] *= cw1;
        }

        // ---- weights + packed P store (warp-private rows) ----
        float zp0 = 0.f, zp1 = 0.f, wp0 = 0.f, wp1 = 0.f;
#pragma unroll
        for (int nt = 0; nt < 8; nt++) {
            float e0 = __expf(s[nt][0] - m0), e1 = __expf(s[nt][1] - m0);
            float e2 = __expf(s[nt][2] - m1), e3 = __expf(s[nt][3] - m1);
            zp0 += e0 + e1; zp1 += e2 + e3;
            float w0, w1, w2, w3;
            if (g2) { w0 = e0 * e0; w1 = e1 * e1; w2 = e2 * e2; w3 = e3 * e3; }
            else {
                w0 = __expf(gam * (s[nt][0] - m0)); w1 = __expf(gam * (s[nt][1] - m0));
                w2 = __expf(gam * (s[nt][2] - m1)); w3 = __expf(gam * (s[nt][3] - m1));
            }
            wp0 += w0 + w1; wp1 += w2 + w3;
            int k2 = nt * 4 + tg;
            smu[FPH + (qb + g) * 36 + k2]     = packhi2(w0, w1);
            smu[FPL + (qb + g) * 36 + k2]     = packlo2(w0, w1);
            smu[FPH + (qb + g + 8) * 36 + k2] = packhi2(w2, w3);
            smu[FPL + (qb + g + 8) * 36 + k2] = packlo2(w2, w3);
        }
        Z0 += zp0; Z1 += zp1; S20 += wp0; S21 += wp1;
        __syncwarp();

        // ---- O += P V ----
#pragma unroll
        for (int ks = 0; ks < 4; ks++) {
            const int kb = ks * 8;       // P word base (keys)
            const int k0 = ks * 16;      // V row base (keys)
            uint32_t ph[4], pl[4];
            ldmx4(ph, sb + (uint32_t)(FPH + (qb + r16) * 36 + kb + kA) * 4);
            ldmx4(pl, sb + (uint32_t)(FPL + (qb + r16) * 36 + kb + kA) * 4);
#pragma unroll
            for (int dp = 0; dp < 4; dp++) {
                uint32_t th[4], tl[4];
                ldmx4t(th, sb + (uint32_t)(FVH + bko + (k0 + r16) * 36 + dp * 8 + kA) * 4);
                ldmx4t(tl, sb + (uint32_t)(FVL + bko + (k0 + r16) * 36 + dp * 8 + kA) * 4);
                mma16(o[2*dp],   ph, &th[0]); mma16(o[2*dp],   ph, &tl[0]); mma16(o[2*dp],   pl, &th[0]);
                mma16(o[2*dp+1], ph, &th[2]); mma16(o[2*dp+1], ph, &tl[2]); mma16(o[2*dp+1], pl, &th[2]);
            }
        }

        if (ch < 31) { stsKV((ch + 1) & 1); __syncthreads(); }
    }

    // ---- final reduce + write ----
    Z0  += __shfl_xor_sync(0xffffffffu, Z0, 1);  Z0  += __shfl_xor_sync(0xffffffffu, Z0, 2);
    Z1  += __shfl_xor_sync(0xffffffffu, Z1, 1);  Z1  += __shfl_xor_sync(0xffffffffu, Z1, 2);
    S20 += __shfl_xor_sync(0xffffffffu, S20, 1); S20 += __shfl_xor_sync(0xffffffffu, S20, 2);
    S21 += __shfl_xor_sync(0xffffffffu, S21, 1); S21 += __shfl_xor_sync(0xffffffffu, S21, 2);

    float Zg0 = g2 ? Z0 * Z0 : __powf(Z0, gam);
    float Zg1 = g2 ? Z1 * Z1 : __powf(Z1, gam);
    float sc0 = alpha / (alpha * S20 + 1e-6f * Zg0);
    float sc1 = alpha / (alpha * S21 + 1e-6f * Zg1);

    const int b = bh >> 4, h = bh & 15;
    const int qA = q0 + qb + g, qB = qA + 8;
#pragma unroll
    for (int nt = 0; nt < 8; nt++) {
        int d = nt * 8 + 2 * tg;
        *(float2*)&g_AO[((size_t)b * NSEQ + qA) * DIM_ + h * HD_ + d] =
            make_float2(o[nt][0] * sc0, o[nt][1] * sc0);
        *(float2*)&g_AO[((size_t)b * NSEQ + qB) * DIM_ + h * HD_ + d] =
            make_float2(o[nt][2] * sc1, o[nt][3] * sc1);
    }
}

// ---------------------------------------------------------------------------
extern "C" void kernel_launch(void* const* d_in, const int* in_sizes, int n_in,
                              void* d_out, int out_size)
{
    const float* x = nullptr, *Wqkv = nullptr, *bqkv = nullptr;
    const float* Wproj = nullptr, *bproj = nullptr, *fa = nullptr, *fg = nullptr;
    for (int i = 0; i < n_in; i++) {
        int sz = in_sizes[i];
        const float* p = (const float*)d_in[i];
        if      (sz == B_*NSEQ*DIM_)   x = p;
        else if (sz == 3*DIM_*DIM_)    Wqkv = p;
        else if (sz == 3*DIM_)         bqkv = p;
        else if (sz == DIM_*DIM_)      Wproj = p;
        else if (sz == DIM_)           bproj = p;
        else if (sz == 1)              { if (!fa) fa = p; else fg = p; }
    }
    float* out = (float*)d_out;

    cudaFuncSetAttribute(tc_gemm<0>,   cudaFuncAttributeMaxDynamicSharedMemorySize, GEMM_SMEM);
    cudaFuncSetAttribute(tc_gemm<1>,   cudaFuncAttributeMaxDynamicSharedMemorySize, GEMM_SMEM);
    cudaFuncSetAttribute(flash_kernel, cudaFuncAttributeMaxDynamicSharedMemorySize, FLASH_SMEM);

    // 1) Fused QKV projection -> Q(scaled)/K/V
    tc_gemm<0><<<dim3(3*DIM_/128, (B_*NSEQ)/128), 256, GEMM_SMEM>>>(x, Wqkv, bqkv, nullptr);
    // 2) Focal flash attention -> g_AO
    flash_kernel<<<dim3(NSEQ/128, B_*H_), 256, FLASH_SMEM>>>(fa, fg);
    // 3) Output projection
    tc_gemm<1><<<dim3(DIM_/128, (B_*NSEQ)/128), 256, GEMM_SMEM>>>(nullptr, Wproj, bproj, out);
}